// round 9
// baseline (speedup 1.0000x reference)
#include <cuda_runtime.h>
#include <cuda_bf16.h>
#include <stdint.h>
#include <math.h>

#define BATCH 4096
#define NROWS 8192
#define DIM   128
#define INV_T 2.0f            // 1 / 0.5

#define BM 128
#define BN 128
#define NSPLIT 16
#define TILES_PER_CTA 4       // 8192 / 128 / 16  (col tiles per CTA)
#define NTHR 512

#define PADF 136              // floats per smem tile row (bank-stagger 8)
#define PAD2 68               // float2 per row
#define ROWB (PADF * 4)       // 544 bytes
#define TILE_SMEM (BM * ROWB) // 69632 bytes per tile buffer

// ---------------- device scratch (allocation-free) ----------------
__device__ float g_z[NROWS * DIM];                    // normalized fp32 (k_pos)
__device__ __align__(16) float g_zt[NROWS * DIM];     // tf32-rounded, (k,k+4)-interleaved
__device__ float g_pos[BATCH];
__device__ float g_denom[NROWS];

// ---------------- helpers ----------------
__device__ __forceinline__ uint32_t sptr(const void* p) {
    uint32_t a;
    asm("{ .reg .u64 t; cvta.to.shared.u64 t, %1; cvt.u32.u64 %0, t; }"
        : "=r"(a) : "l"(p));
    return a;
}
__device__ __forceinline__ uint32_t to_tf32(float f) {
    uint32_t r;
    asm("cvt.rna.tf32.f32 %0, %1;" : "=r"(r) : "f"(f));
    return r;
}

// mma.sync m16n8k8 tf32: c += a * b
__device__ __forceinline__ void mma_tf32(float* c, float2 ag, float2 ag8, float2 b) {
    uint32_t a0 = __float_as_uint(ag.x),  a1 = __float_as_uint(ag8.x);
    uint32_t a2 = __float_as_uint(ag.y),  a3 = __float_as_uint(ag8.y);
    uint32_t b0 = __float_as_uint(b.x),   b1 = __float_as_uint(b.y);
    asm volatile(
        "mma.sync.aligned.m16n8k8.row.col.f32.tf32.tf32.f32 "
        "{%0,%1,%2,%3}, {%4,%5,%6,%7}, {%8,%9}, {%0,%1,%2,%3};"
        : "+f"(c[0]), "+f"(c[1]), "+f"(c[2]), "+f"(c[3])
        : "r"(a0), "r"(a1), "r"(a2), "r"(a3), "r"(b0), "r"(b1));
}

#define CP_ASYNC16(dst_u32, src_ptr) \
    asm volatile("cp.async.cg.shared.global [%0], [%1], 16;" \
                 :: "r"(dst_u32), "l"(src_ptr) : "memory")
#define CP_COMMIT() asm volatile("cp.async.commit_group;" ::: "memory")
#define CP_WAIT0()  asm volatile("cp.async.wait_group 0;" ::: "memory")

// stage a 128x128 float tile (pair-interleaved layout preserved) into padded smem
__device__ __forceinline__ void stage_tile(char* dst, const float* src,
                                           int tid, int nthr) {
    #pragma unroll
    for (int i = tid; i < 4096; i += nthr) {      // 4096 16B chunks
        int row = i >> 5;
        int cs  = i & 31;
        uint32_t d = sptr(dst + row * ROWB + cs * 16);
        const char* s = (const char*)(src + (size_t)row * DIM) + cs * 16;
        CP_ASYNC16(d, s);
    }
}

// exp(2s) via degree-6 Taylor on y=s/2 + two squarings; scalar FFMA-imm forms
__device__ __forceinline__ void epi_elem(float &cv, float &rs) {
    float y = cv * 0.5f;
    float p = fmaf(y, 1.38888888889e-3f, 8.33333333333e-3f);  // y/720 + 1/120
    p = fmaf(p, y, 4.16666666667e-2f);                        // + 1/24
    p = fmaf(p, y, 1.66666666667e-1f);                        // + 1/6
    p = fmaf(p, y, 0.5f);
    p = fmaf(p, y, 1.0f);
    p = fmaf(p, y, 1.0f);                                     // ~= exp(y)
    p = p * p;                                                // exp(s)
    p = p * p;                                                // exp(2s)
    rs += p;
    cv = 0.0f;
}

// ---------------- kernels ----------------
__global__ void k_norm(const float* __restrict__ ei, const float* __restrict__ ej) {
    int w    = (blockIdx.x * blockDim.x + threadIdx.x) >> 5;
    int lane = threadIdx.x & 31;
    if (w >= NROWS) return;
    if (lane == 0) g_denom[w] = 0.0f;     // fused init
    const float* src = (w < BATCH) ? (ei + (size_t)w * DIM)
                                   : (ej + (size_t)(w - BATCH) * DIM);
    float4 v = ((const float4*)src)[lane];
    float ss = v.x*v.x + v.y*v.y + v.z*v.z + v.w*v.w;
    #pragma unroll
    for (int o = 16; o; o >>= 1) ss += __shfl_xor_sync(0xffffffffu, ss, o);
    float s = 1.0f / fmaxf(sqrtf(ss), 1e-12f);
    v.x *= s; v.y *= s; v.z *= s; v.w *= s;
    ((float4*)(g_z + (size_t)w * DIM))[lane] = v;

    // tf32-round + (k, k+4) pair-interleave within each 8-block:
    // k = 8b + p  ->  slot = 8b + (p&3)*2 + (p>>2)
    float vv[4] = { v.x, v.y, v.z, v.w };
    #pragma unroll
    for (int c = 0; c < 4; ++c) {
        int k = lane * 4 + c;
        int b = k >> 3, p = k & 7;
        int slot = b * 8 + (p & 3) * 2 + (p >> 2);
        g_zt[(size_t)w * DIM + slot] = __uint_as_float(to_tf32(vv[c]));
    }
}

__global__ void k_pos() {
    int w    = (blockIdx.x * blockDim.x + threadIdx.x) >> 5;
    int lane = threadIdx.x & 31;
    if (w >= BATCH) return;
    float4 a = ((const float4*)(g_z + (size_t)w * DIM))[lane];
    float4 b = ((const float4*)(g_z + (size_t)(w + BATCH) * DIM))[lane];
    float d = a.x*b.x + a.y*b.y + a.z*b.z + a.w*b.w;
    #pragma unroll
    for (int o = 16; o; o >>= 1) d += __shfl_xor_sync(0xffffffffu, d, o);
    if (lane == 0) g_pos[w] = d;
}

// ---------------- main: tf32 mma.sync GEMM + tile-lagged poly-exp epilogue ----------------
__global__ void __launch_bounds__(NTHR, 1) k_main() {
    extern __shared__ char smem[];
    char* AsB     = smem;
    char* BsB[2]  = { smem + TILE_SMEM, smem + 2 * TILE_SMEM };

    const int tid  = threadIdx.x;
    const int wid  = tid >> 5;
    const int lane = tid & 31;
    const int g    = lane >> 2;         // 0..7
    const int q    = lane & 3;          // 0..3
    const int wm   = wid >> 2;          // 0..3  (M warp, 32 rows each)
    const int wn   = wid & 3;           // 0..3  (N warp, 32 cols each)
    const int rowStart = blockIdx.x * BM;
    const int colBase  = blockIdx.y * (TILES_PER_CTA * BN);

    // prologue: stage A tile + B tile 0
    stage_tile(AsB,    g_zt + (size_t)rowStart * DIM, tid, NTHR);
    stage_tile(BsB[0], g_zt + (size_t)colBase  * DIM, tid, NTHR);
    CP_COMMIT();
    CP_WAIT0();
    __syncthreads();

    const float2* As2 = (const float2*)AsB;

    // two C sets (ping-pong): C[set][i][j][reg] ; warp tile 32x32 -> i:2, j:4
    float C[2][2][4][4];
    #pragma unroll
    for (int s = 0; s < 2; s++)
        #pragma unroll
        for (int i = 0; i < 2; i++)
            #pragma unroll
            for (int j = 0; j < 4; j++)
                #pragma unroll
                for (int e = 0; e < 4; e++) C[s][i][j][e] = 0.0f;

    float rs[2][2] = {{0.0f, 0.0f}, {0.0f, 0.0f}};   // [i][rowhalf]

    #pragma unroll
    for (int t = 0; t < TILES_PER_CTA; ++t) {
        if (t + 1 < TILES_PER_CTA) {
            stage_tile(BsB[(t + 1) & 1],
                       g_zt + (size_t)(colBase + (t + 1) * BN) * DIM, tid, NTHR);
        }
        CP_COMMIT();

        const float2* Bs2 = (const float2*)BsB[t & 1];
        const int cur = t & 1, prv = 1 - cur;

        #pragma unroll
        for (int ks = 0; ks < 16; ++ks) {
            float2 a0[2], a1[2], bb[4];
            #pragma unroll
            for (int i = 0; i < 2; i++) {
                int r0 = wm * 32 + i * 16 + g;
                a0[i] = As2[r0 * PAD2 + ks * 4 + q];
                a1[i] = As2[(r0 + 8) * PAD2 + ks * 4 + q];
            }
            #pragma unroll
            for (int j = 0; j < 4; j++) {
                int n0 = wn * 32 + j * 8 + g;
                bb[j] = Bs2[n0 * PAD2 + ks * 4 + q];
            }
            #pragma unroll
            for (int i = 0; i < 2; i++)
                #pragma unroll
                for (int j = 0; j < 4; j++)
                    mma_tf32(C[cur][i][j], a0[i], a1[i], bb[j]);

            // lagged epilogue: 2 elements of the previous tile's C per ks step
            if (t > 0) {
                #pragma unroll
                for (int u = 0; u < 2; ++u) {
                    int e = ks * 2 + u;          // 0..31
                    int i = e >> 4, rem = e & 15;
                    int j = rem >> 2, r = rem & 3;
                    epi_elem(C[prv][i][j][r], rs[i][r >> 1]);
                }
            }
        }

        CP_WAIT0();
        __syncthreads();
    }

    // final epilogue for the last tile's C (set = (TILES_PER_CTA-1)&1)
    #pragma unroll
    for (int e = 0; e < 32; ++e) {
        int i = e >> 4, rem = e & 15;
        int j = rem >> 2, r = rem & 3;
        epi_elem(C[(TILES_PER_CTA - 1) & 1][i][j][r], rs[i][r >> 1]);
    }

    // reduce: quad lanes (q=0..3) hold different columns of the same rows
    float* red = (float*)smem;   // [128][4]
    #pragma unroll
    for (int i = 0; i < 2; i++) {
        #pragma unroll
        for (int h = 0; h < 2; h++) {
            float v = rs[i][h];
            v += __shfl_xor_sync(0xffffffffu, v, 1);
            v += __shfl_xor_sync(0xffffffffu, v, 2);
            if (q == 0) {
                int row = wm * 32 + i * 16 + h * 8 + g;
                red[row * 4 + wn] = v;
            }
        }
    }
    __syncthreads();
    if (tid < BM) {
        float s = red[tid * 4] + red[tid * 4 + 1] + red[tid * 4 + 2] + red[tid * 4 + 3];
        int r = rowStart + tid;
        // remove diagonal term (present in exactly one col-group): exp(2*sim_rr) ~ e^2
        if ((r >> 9) == (int)blockIdx.y) s -= 7.3890560989306495f;
        atomicAdd(&g_denom[r], s);
    }
}

// ---------------- final loss reduction ----------------
__global__ void k_loss(float* __restrict__ out) {
    int tid = threadIdx.x;
    float s = 0.0f;
    for (int r = tid; r < NROWS; r += 256) {
        float p = g_pos[(r < BATCH) ? r : (r - BATCH)];
        s += logf(g_denom[r]) - p * INV_T;
    }
    __shared__ float red[256];
    red[tid] = s;
    __syncthreads();
    #pragma unroll
    for (int st = 128; st; st >>= 1) {
        if (tid < st) red[tid] += red[tid + st];
        __syncthreads();
    }
    if (tid == 0) out[0] = red[0] / (float)NROWS;
}

extern "C" void kernel_launch(void* const* d_in, const int* in_sizes, int n_in,
                              void* d_out, int out_size) {
    const float* emb_i = (const float*)d_in[0];
    const float* emb_j = (const float*)d_in[1];
    float* out = (float*)d_out;
    (void)in_sizes; (void)n_in; (void)out_size;

    cudaFuncSetAttribute(k_main, cudaFuncAttributeMaxDynamicSharedMemorySize,
                         3 * TILE_SMEM);

    k_norm<<<NROWS / 8, 256>>>(emb_i, emb_j);
    k_pos<<<BATCH / 8, 256>>>();
    dim3 grid(NROWS / BM, NSPLIT);
    k_main<<<grid, NTHR, 3 * TILE_SMEM>>>();
    k_loss<<<1, 256>>>(out);
}

// round 10
// speedup vs baseline: 1.6125x; 1.6125x over previous
#include <cuda_runtime.h>
#include <cuda_bf16.h>
#include <stdint.h>
#include <math.h>

#define BATCH 4096
#define NROWS 8192
#define DIM   128
#define INV_T 2.0f            // 1 / 0.5
#define NTILE 64              // 8192 / 128

#define BM 128
#define BN 128
#define NTHR 256

#define PADF 136              // floats per smem tile row (bank-stagger 8)
#define PAD2 68               // float2 per row
#define ROWB (PADF * 4)       // 544 bytes
#define TILE_SMEM (BM * ROWB) // 69632 bytes per tile buffer

// ---------------- device scratch (allocation-free) ----------------
__device__ __align__(16) float g_zt[NROWS * DIM];  // tf32-rounded, (k,k+4)-interleaved
__device__ float g_pos[BATCH];
__device__ float g_denom[NROWS];

// ---------------- helpers ----------------
__device__ __forceinline__ uint32_t sptr(const void* p) {
    uint32_t a;
    asm("{ .reg .u64 t; cvta.to.shared.u64 t, %1; cvt.u32.u64 %0, t; }"
        : "=r"(a) : "l"(p));
    return a;
}
__device__ __forceinline__ uint32_t to_tf32(float f) {
    uint32_t r;
    asm("cvt.rna.tf32.f32 %0, %1;" : "=r"(r) : "f"(f));
    return r;
}

// mma.sync m16n8k8 tf32: c += a * b
__device__ __forceinline__ void mma_tf32(float* c, float2 ag, float2 ag8, float2 b) {
    uint32_t a0 = __float_as_uint(ag.x),  a1 = __float_as_uint(ag8.x);
    uint32_t a2 = __float_as_uint(ag.y),  a3 = __float_as_uint(ag8.y);
    uint32_t b0 = __float_as_uint(b.x),   b1 = __float_as_uint(b.y);
    asm volatile(
        "mma.sync.aligned.m16n8k8.row.col.f32.tf32.tf32.f32 "
        "{%0,%1,%2,%3}, {%4,%5,%6,%7}, {%8,%9}, {%0,%1,%2,%3};"
        : "+f"(c[0]), "+f"(c[1]), "+f"(c[2]), "+f"(c[3])
        : "r"(a0), "r"(a1), "r"(a2), "r"(a3), "r"(b0), "r"(b1));
}

#define CP_ASYNC16(dst_u32, src_ptr) \
    asm volatile("cp.async.cg.shared.global [%0], [%1], 16;" \
                 :: "r"(dst_u32), "l"(src_ptr) : "memory")
#define CP_COMMIT() asm volatile("cp.async.commit_group;" ::: "memory")
#define CP_WAIT1()  asm volatile("cp.async.wait_group 1;" ::: "memory")
#define CP_WAIT0()  asm volatile("cp.async.wait_group 0;" ::: "memory")

// stage one K-half (64 k-slots = 16 16B-chunks per row) of a 128-row tile
__device__ __forceinline__ void stage_half(char* dst, const float* src,
                                           int tid, int half) {
    #pragma unroll
    for (int i = tid; i < 2048; i += NTHR) {      // 2048 16B chunks per half
        int row = i >> 4;
        int cs  = (i & 15) + half * 16;
        uint32_t d = sptr(dst + row * ROWB + cs * 16);
        const char* s = (const char*)(src + (size_t)row * DIM) + cs * 16;
        CP_ASYNC16(d, s);
    }
}

// exp(2s) via degree-6 Taylor on y=s/2 + two squarings (|s|<=1 -> rel err ~1e-6)
__device__ __forceinline__ float exp2s(float s) {
    float y = s * 0.5f;
    float p = fmaf(y, 1.38888888889e-3f, 8.33333333333e-3f);
    p = fmaf(p, y, 4.16666666667e-2f);
    p = fmaf(p, y, 1.66666666667e-1f);
    p = fmaf(p, y, 0.5f);
    p = fmaf(p, y, 1.0f);
    p = fmaf(p, y, 1.0f);     // ~= exp(y)
    p = p * p;                // exp(s)
    return p * p;             // exp(2s)
}

// ---------------- k_norm: normalize + tf32 store + fused positives + denom init ----------------
__global__ void k_norm(const float* __restrict__ ei, const float* __restrict__ ej) {
    int w    = (blockIdx.x * blockDim.x + threadIdx.x) >> 5;
    int lane = threadIdx.x & 31;
    if (w >= NROWS) return;
    if (lane == 0) g_denom[w] = 0.0f;     // fused init

    const float* src = (w < BATCH) ? (ei + (size_t)w * DIM)
                                   : (ej + (size_t)(w - BATCH) * DIM);
    float4 v = ((const float4*)src)[lane];
    float ss = v.x*v.x + v.y*v.y + v.z*v.z + v.w*v.w;

    if (w < BATCH) {
        // fused positives: dot(ei,ej) / (|ei| |ej|)
        float4 u = ((const float4*)(ej + (size_t)w * DIM))[lane];
        float s2 = u.x*u.x + u.y*u.y + u.z*u.z + u.w*u.w;
        float dt = v.x*u.x + v.y*u.y + v.z*u.z + v.w*u.w;
        #pragma unroll
        for (int o = 16; o; o >>= 1) {
            ss += __shfl_xor_sync(0xffffffffu, ss, o);
            s2 += __shfl_xor_sync(0xffffffffu, s2, o);
            dt += __shfl_xor_sync(0xffffffffu, dt, o);
        }
        if (lane == 0)
            g_pos[w] = dt / (fmaxf(sqrtf(ss), 1e-12f) * fmaxf(sqrtf(s2), 1e-12f));
    } else {
        #pragma unroll
        for (int o = 16; o; o >>= 1) ss += __shfl_xor_sync(0xffffffffu, ss, o);
    }

    float s = 1.0f / fmaxf(sqrtf(ss), 1e-12f);
    float vv[4] = { v.x * s, v.y * s, v.z * s, v.w * s };
    // tf32-round + (k, k+4) pair-interleave within each 8-block:
    // k = 8b + p  ->  slot = 8b + (p&3)*2 + (p>>2)
    #pragma unroll
    for (int c = 0; c < 4; ++c) {
        int k = lane * 4 + c;
        int b = k >> 3, p = k & 7;
        int slot = b * 8 + (p & 3) * 2 + (p >> 2);
        g_zt[(size_t)w * DIM + slot] = __uint_as_float(to_tf32(vv[c]));
    }
}

// ---------------- main: symmetric (upper-triangle) tf32 GEMM + fused exp ----------------
// grid (64, 33): by==0 -> diagonal tile (bi,bi); by 1..32 -> pair {bi, (bi+by)&63}
// (by==32 valid only for bi<32). Each unordered tile pair computed exactly once;
// exp sums scattered to row-denoms (A side) and col-denoms (B side).
__global__ void __launch_bounds__(NTHR, 1) k_main() {
    const int bi = blockIdx.x;
    const int by = blockIdx.y;
    if (by == 32 && bi >= 32) return;
    const int bj   = (bi + by) & (NTILE - 1);
    const bool diag = (by == 0);

    extern __shared__ char smem[];
    char* AsB = smem;
    char* BsB = smem + TILE_SMEM;

    const int tid  = threadIdx.x;
    const int wid  = tid >> 5;
    const int lane = tid & 31;
    const int g    = lane >> 2;         // 0..7
    const int q    = lane & 3;          // 0..3
    const int wm   = wid >> 2;          // 0..1  (M warp, 64 rows)
    const int wn   = wid & 3;           // 0..3  (N warp, 32 cols)
    const int rowStart = bi * BM;
    const int colStart = bj * BN;

    const float* srcA = g_zt + (size_t)rowStart * DIM;
    const float* srcB = g_zt + (size_t)colStart * DIM;

    // stage both tiles, split by K-half for load/compute overlap
    stage_half(AsB, srcA, tid, 0);
    stage_half(BsB, srcB, tid, 0);
    CP_COMMIT();
    stage_half(AsB, srcA, tid, 1);
    stage_half(BsB, srcB, tid, 1);
    CP_COMMIT();

    const float2* As2 = (const float2*)AsB;
    const float2* Bs2 = (const float2*)BsB;

    float C[4][4][4];
    #pragma unroll
    for (int i = 0; i < 4; i++)
        #pragma unroll
        for (int j = 0; j < 4; j++)
            #pragma unroll
            for (int e = 0; e < 4; e++) C[i][j][e] = 0.0f;

    CP_WAIT1();
    __syncthreads();

    #pragma unroll
    for (int kh = 0; kh < 2; ++kh) {
        if (kh == 1) { CP_WAIT0(); __syncthreads(); }
        #pragma unroll
        for (int ki = 0; ki < 8; ++ki) {
            const int ks = kh * 8 + ki;
            float2 a0[4], a1[4], bb[4];
            #pragma unroll
            for (int i = 0; i < 4; i++) {
                int r0 = wm * 64 + i * 16 + g;
                a0[i] = As2[r0 * PAD2 + ks * 4 + q];
                a1[i] = As2[(r0 + 8) * PAD2 + ks * 4 + q];
            }
            #pragma unroll
            for (int j = 0; j < 4; j++) {
                int n0 = wn * 32 + j * 8 + g;
                bb[j] = Bs2[n0 * PAD2 + ks * 4 + q];
            }
            #pragma unroll
            for (int i = 0; i < 4; i++)
                #pragma unroll
                for (int j = 0; j < 4; j++)
                    mma_tf32(C[i][j], a0[i], a1[i], bb[j]);
        }
    }

    // epilogue: exp(2*sim); accumulate row sums (always) and col sums (off-diag)
    float rs[4][2];                 // [i][rowhalf]
    float cs[8];                    // [j*2 + colparity]
    #pragma unroll
    for (int i = 0; i < 4; i++) { rs[i][0] = 0.0f; rs[i][1] = 0.0f; }
    #pragma unroll
    for (int e = 0; e < 8; e++) cs[e] = 0.0f;

    #pragma unroll
    for (int i = 0; i < 4; i++)
        #pragma unroll
        for (int j = 0; j < 4; j++)
            #pragma unroll
            for (int r = 0; r < 4; r++) {
                float ev = exp2s(C[i][j][r]);
                rs[i][r >> 1] += ev;
                cs[j * 2 + (r & 1)] += ev;
            }

    __syncthreads();   // all mma reads of As/Bs done; reuse smem for reductions
    float* red  = (float*)smem;            // [128][4] row partials per wn
    float* redc = (float*)smem + 512;      // [128][2] col partials per wm

    // row sums: reduce over q (cols within quad)
    #pragma unroll
    for (int i = 0; i < 4; i++) {
        #pragma unroll
        for (int h = 0; h < 2; h++) {
            float v = rs[i][h];
            v += __shfl_xor_sync(0xffffffffu, v, 1);
            v += __shfl_xor_sync(0xffffffffu, v, 2);
            if (q == 0) {
                int row = wm * 64 + i * 16 + h * 8 + g;
                red[row * 4 + wn] = v;
            }
        }
    }
    // col sums: reduce over g (rows within warp)
    if (!diag) {
        #pragma unroll
        for (int e = 0; e < 8; e++) {
            float v = cs[e];
            v += __shfl_xor_sync(0xffffffffu, v, 4);
            v += __shfl_xor_sync(0xffffffffu, v, 8);
            v += __shfl_xor_sync(0xffffffffu, v, 16);
            if (g == 0) {
                int col = wn * 32 + (e >> 1) * 8 + q * 2 + (e & 1);
                redc[col * 2 + wm] = v;
            }
        }
    }
    __syncthreads();

    if (tid < BM) {
        float s = red[tid * 4] + red[tid * 4 + 1] + red[tid * 4 + 2] + red[tid * 4 + 3];
        if (diag) s -= 7.3890560989306495f;   // remove exp(2*sim_rr) ~ e^2
        atomicAdd(&g_denom[rowStart + tid], s);
        if (!diag) {
            float c = redc[tid * 2] + redc[tid * 2 + 1];
            atomicAdd(&g_denom[colStart + tid], c);
        }
    }
}

// ---------------- final loss reduction ----------------
__global__ void k_loss(float* __restrict__ out) {
    int tid = threadIdx.x;
    float s = 0.0f;
    for (int r = tid; r < NROWS; r += 1024) {
        float p = g_pos[(r < BATCH) ? r : (r - BATCH)];
        s += logf(g_denom[r]) - p * INV_T;
    }
    __shared__ float red[1024];
    red[tid] = s;
    __syncthreads();
    #pragma unroll
    for (int st = 512; st; st >>= 1) {
        if (tid < st) red[tid] += red[tid + st];
        __syncthreads();
    }
    if (tid == 0) out[0] = red[0] / (float)NROWS;
}

extern "C" void kernel_launch(void* const* d_in, const int* in_sizes, int n_in,
                              void* d_out, int out_size) {
    const float* emb_i = (const float*)d_in[0];
    const float* emb_j = (const float*)d_in[1];
    float* out = (float*)d_out;
    (void)in_sizes; (void)n_in; (void)out_size;

    cudaFuncSetAttribute(k_main, cudaFuncAttributeMaxDynamicSharedMemorySize,
                         2 * TILE_SMEM);

    k_norm<<<NROWS / 8, 256>>>(emb_i, emb_j);
    dim3 grid(NTILE, 33);
    k_main<<<grid, NTHR, 2 * TILE_SMEM>>>();
    k_loss<<<1, 1024>>>(out);
}